// round 12
// baseline (speedup 1.0000x reference)
#include <cuda_runtime.h>

// PIANO_EnergyV on (2,160,160,160) fp32, h=1.
// Round 8: same merged interior/boundary kernel, but register-dieted:
//  - central gradients recomputed per group (no persistent cXC/cYC/cZC arrays)
//  - load groups split to <=6 concurrent row-arrays
//  - __launch_bounds__(160, 6) to force >=6 blocks/SM (occupancy lever)

#define NN 160
#define SX (NN*NN)
#define SY (NN)
#define NINT (40 * (NN - 2))          // 6320 interior blocks per batch
#define NBND (2 * NN + 2 * (NN - 2))  // 636 boundary row-blocks per batch

__device__ __forceinline__ float4 ldg4(const float* __restrict__ p) {
    return *reinterpret_cast<const float4*>(p);
}

// Row indexing: r[k] holds value at z = z0 - 1 + k.
#define LOAD_MID4(dst, P, B) do { \
    float4 _q = ldg4((P) + (B) + z0); \
    dst[1] = _q.x; dst[2] = _q.y; dst[3] = _q.z; dst[4] = _q.w; } while (0)
#define LOAD_LO5(dst, P, B) do { \
    LOAD_MID4(dst, P, B); \
    dst[0] = lo_ok ? (P)[(B) + z0 - 1] : dst[1]; } while (0)
#define LOAD_HI5(dst, P, B) do { \
    LOAD_MID4(dst, P, B); \
    dst[5] = hi_ok ? (P)[(B) + z0 + 4] : dst[4]; } while (0)
#define LOAD_FULL6(dst, P, B) do { \
    LOAD_MID4(dst, P, B); \
    dst[0] = lo_ok ? (P)[(B) + z0 - 1] : dst[1]; \
    dst[5] = hi_ok ? (P)[(B) + z0 + 4] : dst[4]; } while (0)

// Recomputed central gradients (C rows are always live)
#define CXC(k) ((cxp[k] - cxm[k]) * 0.5f)
#define CYC(k) ((cyp[k] - cym[k]) * 0.5f)
#define CZC(k, zlo, zhi) \
    ((zlo) ? (c00[(k)+1] - c00[k]) \
   : (zhi) ? (c00[k]   - c00[(k)-1]) \
           : (c00[(k)+1] - c00[(k)-1]) * 0.5f)

// ---------------------------------------------------------------------------
// Interior path: x in [1,158], y in [1,158], 4 z-voxels per thread.
// ---------------------------------------------------------------------------
__device__ __forceinline__ void interior_path(
    int bx, int b,
    const float* __restrict__ C_,
    const float* __restrict__ Vx_,
    const float* __restrict__ Vy_,
    const float* __restrict__ Vz_,
    const float* __restrict__ Dxx_,
    const float* __restrict__ Dxy_,
    const float* __restrict__ Dxz_,
    const float* __restrict__ Dyy_,
    const float* __restrict__ Dyz_,
    const float* __restrict__ Dzz_,
    float* __restrict__ out)
{
    const int tid = threadIdx.x;
    const int t  = tid % 40;            // z chunk
    const int ys = tid / 40;            // y sub-row
    const int yq = bx % 40;
    const int x  = 1 + bx / 40;
    const int y  = 1 + 4 * yq + ys;
    if (y > NN - 2) return;
    const int z0 = 4 * t;
    const int base = ((b * NN + x) * NN + y) * NN;
    const bool lo_ok = (t > 0);
    const bool hi_ok = (t < 39);

    // ---- C rows (live throughout) ----
    float c00[6], cxm[6], cxp[6], cym[6], cyp[6];
    LOAD_FULL6(c00, C_, base);
    LOAD_HI5 (cxm, C_, base - SX);
    LOAD_LO5 (cxp, C_, base + SX);
    LOAD_HI5 (cym, C_, base - SY);
    LOAD_LO5 (cyp, C_, base + SY);

    float res[4];

    // ==== G1: Dxx + Dyy (6 MID4 arrays) ====
    {
        float axc[6], axm[6], axp[6], ayc[6], aym[6], ayp[6];
        LOAD_MID4(axc, Dxx_, base);
        LOAD_MID4(axm, Dxx_, base - SX);
        LOAD_MID4(axp, Dxx_, base + SX);
        LOAD_MID4(ayc, Dyy_, base);
        LOAD_MID4(aym, Dyy_, base - SY);
        LOAD_MID4(ayp, Dyy_, base + SY);
        #pragma unroll
        for (int e = 0; e < 4; e++) { const int k = e + 1;
            float sxx = cxp[k] - 2.0f * c00[k] + cxm[k];
            float syy = cyp[k] - 2.0f * c00[k] + cym[k];
            res[e] = (axp[k] - axm[k]) * 0.5f * CXC(k) + axc[k] * sxx
                   + (ayp[k] - aym[k]) * 0.5f * CYC(k) + ayc[k] * syy;
        }
    }
    // ==== G2: Dzz (1 FULL6 array) ====
    {
        float azc[6];
        LOAD_FULL6(azc, Dzz_, base);
        #pragma unroll
        for (int e = 0; e < 4; e++) { const int k = e + 1;
            const bool zlo = (e == 0) && (t == 0);
            const bool zhi = (e == 3) && (t == 39);
            float cz  = zlo ? (azc[k+1] - azc[k])
                      : zhi ? (azc[k]   - azc[k-1])
                            : (azc[k+1] - azc[k-1]) * 0.5f;
            float szz = zhi ? 0.0f
                      : zlo ? (c00[k+2] - 2.0f * c00[k+1] + c00[k])
                            : (c00[k+1] - 2.0f * c00[k]   + c00[k-1]);
            res[e] += cz * CZC(k, zlo, zhi) + azc[k] * szz;
        }
    }
    // ==== G3: xy-corner C rows -> tmp = mXY + mYX ====
    float tmp[4];
    {
        float cq1[6], cq2[6];
        LOAD_MID4(cq1, C_, base - SX + SY);   // (x-1, y+1)
        LOAD_MID4(cq2, C_, base + SX - SY);   // (x+1, y-1)
        #pragma unroll
        for (int e = 0; e < 4; e++) { const int k = e + 1;
            float mXY = (cyp[k] - c00[k]) - (cq1[k] - cxm[k]);
            float mYX = (cxp[k] - c00[k]) - (cq2[k] - cym[k]);
            tmp[e] = mXY + mYX;
        }
    }
    // ==== G4: Dxy rows (5 MID4 arrays) ====
    {
        float dc[6], dxm2[6], dxp2[6], dym2[6], dyp2[6];
        LOAD_MID4(dc,   Dxy_, base);
        LOAD_MID4(dxm2, Dxy_, base - SX);
        LOAD_MID4(dxp2, Dxy_, base + SX);
        LOAD_MID4(dym2, Dxy_, base - SY);
        LOAD_MID4(dyp2, Dxy_, base + SY);
        #pragma unroll
        for (int e = 0; e < 4; e++) { const int k = e + 1;
            res[e] += (dxp2[k] - dxm2[k]) * 0.5f * CYC(k)
                    + (dyp2[k] - dym2[k]) * 0.5f * CXC(k)
                    + dc[k] * tmp[e];
        }
    }
    // ==== G5: Dxz (FULL6 + 2 MID4) ====
    {
        float ec[6], em[6], ep[6];
        LOAD_FULL6(ec, Dxz_, base);
        LOAD_MID4 (em, Dxz_, base - SX);
        LOAD_MID4 (ep, Dxz_, base + SX);
        #pragma unroll
        for (int e = 0; e < 4; e++) { const int k = e + 1;
            const bool zlo = (e == 0) && (t == 0);
            const bool zhi = (e == 3) && (t == 39);
            float czE = zlo ? (ec[k+1] - ec[k])
                      : zhi ? (ec[k]   - ec[k-1])
                            : (ec[k+1] - ec[k-1]) * 0.5f;
            float czf0 = zhi ? (c00[k] - c00[k-1]) : (c00[k+1] - c00[k]);
            float czfx = zhi ? (cxm[k] - cxm[k-1]) : (cxm[k+1] - cxm[k]);
            float mXZ = czf0 - czfx;
            float mZX = zlo ? ((cxp[k+1] - c00[k+1]) - (cxp[k]   - c00[k]))
                            : ((cxp[k]   - c00[k])   - (cxp[k-1] - c00[k-1]));
            res[e] += czE * CXC(k) + (ep[k] - em[k]) * 0.5f * CZC(k, zlo, zhi)
                    + ec[k] * (mXZ + mZX);
        }
    }
    // ==== G6: Dyz (FULL6 + 2 MID4) ====
    {
        float fc[6], fm[6], fp[6];
        LOAD_FULL6(fc, Dyz_, base);
        LOAD_MID4 (fm, Dyz_, base - SY);
        LOAD_MID4 (fp, Dyz_, base + SY);
        #pragma unroll
        for (int e = 0; e < 4; e++) { const int k = e + 1;
            const bool zlo = (e == 0) && (t == 0);
            const bool zhi = (e == 3) && (t == 39);
            float czF = zlo ? (fc[k+1] - fc[k])
                      : zhi ? (fc[k]   - fc[k-1])
                            : (fc[k+1] - fc[k-1]) * 0.5f;
            float czf0 = zhi ? (c00[k] - c00[k-1]) : (c00[k+1] - c00[k]);
            float czfy = zhi ? (cym[k] - cym[k-1]) : (cym[k+1] - cym[k]);
            float mYZ = czf0 - czfy;
            float mZY = zlo ? ((cyp[k+1] - c00[k+1]) - (cyp[k]   - c00[k]))
                            : ((cyp[k]   - c00[k])   - (cyp[k-1] - c00[k-1]));
            res[e] += czF * CYC(k) + (fp[k] - fm[k]) * 0.5f * CZC(k, zlo, zhi)
                    + fc[k] * (mYZ + mZY);
        }
    }
    // ==== G7: Vx + Vy (6 MID4 arrays) ====
    {
        float vxc[6], vxm[6], vxp[6], vyc[6], vym[6], vyp[6];
        LOAD_MID4(vxc, Vx_, base);
        LOAD_MID4(vxm, Vx_, base - SX);
        LOAD_MID4(vxp, Vx_, base + SX);
        LOAD_MID4(vyc, Vy_, base);
        LOAD_MID4(vym, Vy_, base - SY);
        LOAD_MID4(vyp, Vy_, base + SY);
        #pragma unroll
        for (int e = 0; e < 4; e++) { const int k = e + 1;
            float vx = vxc[k], vy = vyc[k];
            float cux = (vx > 0.0f) ? (c00[k] - cxm[k]) : (cxp[k] - c00[k]);
            float cuy = (vy > 0.0f) ? (c00[k] - cym[k]) : (cyp[k] - c00[k]);
            res[e] += -(vx * cux + vy * cuy)
                    - c00[k] * ((vxp[k] - vxm[k]) * 0.5f + (vyp[k] - vym[k]) * 0.5f);
        }
    }
    // ==== G8: Vz (1 FULL6 array) ====
    {
        float vzc[6];
        LOAD_FULL6(vzc, Vz_, base);
        #pragma unroll
        for (int e = 0; e < 4; e++) { const int k = e + 1;
            const bool zlo = (e == 0) && (t == 0);
            const bool zhi = (e == 3) && (t == 39);
            float vz  = vzc[k];
            float cbz = zlo ? (c00[k+1] - c00[k]) : (c00[k] - c00[k-1]);
            float cfz = zhi ? (c00[k] - c00[k-1]) : (c00[k+1] - c00[k]);
            float cuz = (vz > 0.0f) ? cbz : cfz;
            float dvz = zlo ? (vzc[k+1] - vzc[k])
                      : zhi ? (vzc[k]   - vzc[k-1])
                            : (vzc[k+1] - vzc[k-1]) * 0.5f;
            res[e] += -vz * cuz - c00[k] * dvz;
        }
    }

    float4 o;
    o.x = res[0]; o.y = res[1]; o.z = res[2]; o.w = res[3];
    *reinterpret_cast<float4*>(out + base + z0) = o;
}

// ---------------------------------------------------------------------------
// Boundary path: rows with x in {0,159} (all y) or y in {0,159} (x 1..158).
// Scalar, one thread per voxel, one row per block. (Round-1 proven code.)
// ---------------------------------------------------------------------------
__device__ __forceinline__ void boundary_path(
    int idx, int b,
    const float* __restrict__ C,
    const float* __restrict__ Vx,
    const float* __restrict__ Vy,
    const float* __restrict__ Vz,
    const float* __restrict__ Dxx,
    const float* __restrict__ Dxy,
    const float* __restrict__ Dxz,
    const float* __restrict__ Dyy,
    const float* __restrict__ Dyz,
    const float* __restrict__ Dzz,
    float* __restrict__ out)
{
    int x, y;
    if (idx < 2 * NN) {
        x = (idx < NN) ? 0 : NN - 1;
        y = idx % NN;
    } else {
        int r = idx - 2 * NN;
        x = 1 + (r >> 1);
        y = (r & 1) ? NN - 1 : 0;
    }
    const int z = threadIdx.x;
    const int i = ((b * NN + x) * NN + y) * NN + z;

    const int dxm = (x > 0)      ? -SX : 0;
    const int dxp = (x < NN - 1) ?  SX : 0;
    const float wx = (x > 0 && x < NN - 1) ? 0.5f : 1.0f;
    const int dym = (y > 0)      ? -SY : 0;
    const int dyp = (y < NN - 1) ?  SY : 0;
    const float wy = (y > 0 && y < NN - 1) ? 0.5f : 1.0f;
    const int dzm = (z > 0)      ? -1 : 0;
    const int dzp = (z < NN - 1) ?  1 : 0;
    const float wz = (z > 0 && z < NN - 1) ? 0.5f : 1.0f;

    const int fx0 = (x == NN - 1) ? -SX : 0;  const int fx1 = fx0 + SX;
    const int fy0 = (y == NN - 1) ? -SY : 0;  const int fy1 = fy0 + SY;
    const int fz0 = (z == NN - 1) ? -1  : 0;  const int fz1 = fz0 + 1;

    const int bx1 = (x == 0) ? SX : 0;  const int bx0 = bx1 - SX;
    const int by1 = (y == 0) ? SY : 0;  const int by0 = by1 - SY;
    const int bz1 = (z == 0) ? 1  : 0;  const int bz0 = bz1 - 1;

    const float cXC = (C[i + dxp] - C[i + dxm]) * wx;
    const float cYC = (C[i + dyp] - C[i + dym]) * wy;
    const float cZC = (C[i + dzp] - C[i + dzm]) * wz;

    const float gx = (Dxx[i + dxp] - Dxx[i + dxm]) * wx
                   + (Dxy[i + dyp] - Dxy[i + dym]) * wy
                   + (Dxz[i + dzp] - Dxz[i + dzm]) * wz;
    const float gy = (Dxy[i + dxp] - Dxy[i + dxm]) * wx
                   + (Dyy[i + dyp] - Dyy[i + dym]) * wy
                   + (Dyz[i + dzp] - Dyz[i + dzm]) * wz;
    const float gz = (Dxz[i + dxp] - Dxz[i + dxm]) * wx
                   + (Dyz[i + dyp] - Dyz[i + dym]) * wy
                   + (Dzz[i + dzp] - Dzz[i + dzm]) * wz;

    const float sxx = (x == NN - 1) ? 0.0f
                    : (C[i + bx1 + SX] - 2.0f * C[i + bx1] + C[i + bx1 - SX]);
    const float syy = (y == NN - 1) ? 0.0f
                    : (C[i + by1 + SY] - 2.0f * C[i + by1] + C[i + by1 - SY]);
    const float szz = (z == NN - 1) ? 0.0f
                    : (C[i + bz1 + 1]  - 2.0f * C[i + bz1] + C[i + bz1 - 1]);

    #define MIX(bA1, bA0, fB1, fB0) \
        ((C[i + (bA1) + (fB1)] - C[i + (bA1) + (fB0)]) - \
         (C[i + (bA0) + (fB1)] - C[i + (bA0) + (fB0)]))
    const float mXY = MIX(bx1, bx0, fy1, fy0);
    const float mYX = MIX(by1, by0, fx1, fx0);
    const float mYZ = MIX(by1, by0, fz1, fz0);
    const float mZY = MIX(bz1, bz0, fy1, fy0);
    const float mZX = MIX(bz1, bz0, fx1, fx0);
    const float mXZ = MIX(bx1, bx0, fz1, fz0);
    #undef MIX

    const float diff = gx * cXC + gy * cYC + gz * cZC
                     + Dxx[i] * sxx + Dyy[i] * syy + Dzz[i] * szz
                     + Dxy[i] * (mXY + mYX)
                     + Dyz[i] * (mYZ + mZY)
                     + Dxz[i] * (mZX + mXZ);

    const float vx = Vx[i], vy = Vy[i], vz = Vz[i];
    const float bXC = C[i + bx1] - C[i + bx0];
    const float fXC = C[i + fx1] - C[i + fx0];
    const float bYC = C[i + by1] - C[i + by0];
    const float fYC = C[i + fy1] - C[i + fy0];
    const float bZC = C[i + bz1] - C[i + bz0];
    const float fZC = C[i + fz1] - C[i + fz0];
    const float Cux = (vx > 0.0f) ? bXC : fXC;
    const float Cuy = (vy > 0.0f) ? bYC : fYC;
    const float Cuz = (vz > 0.0f) ? bZC : fZC;

    const float divV = (Vx[i + dxp] - Vx[i + dxm]) * wx
                     + (Vy[i + dyp] - Vy[i + dym]) * wy
                     + (Vz[i + dzp] - Vz[i + dzm]) * wz;

    const float adv = -(vx * Cux + vy * Cuy + vz * Cuz) - C[i] * divV;
    out[i] = diff + adv;
}

// ---------------------------------------------------------------------------
// Merged kernel: blockIdx.x < NINT -> interior; else boundary.
// ---------------------------------------------------------------------------
__global__ __launch_bounds__(160, 6)
void piano_all(
    const float* __restrict__ C,
    const float* __restrict__ Vx,
    const float* __restrict__ Vy,
    const float* __restrict__ Vz,
    const float* __restrict__ Dxx,
    const float* __restrict__ Dxy,
    const float* __restrict__ Dxz,
    const float* __restrict__ Dyy,
    const float* __restrict__ Dyz,
    const float* __restrict__ Dzz,
    float* __restrict__ out)
{
    const int bx = blockIdx.x;
    const int b  = blockIdx.y;
    if (bx < NINT) {
        interior_path(bx, b, C, Vx, Vy, Vz, Dxx, Dxy, Dxz, Dyy, Dyz, Dzz, out);
    } else {
        boundary_path(bx - NINT, b, C, Vx, Vy, Vz,
                      Dxx, Dxy, Dxz, Dyy, Dyz, Dzz, out);
    }
}

extern "C" void kernel_launch(void* const* d_in, const int* in_sizes, int n_in,
                              void* d_out, int out_size)
{
    const float* C   = (const float*)d_in[0];
    const float* Vx  = (const float*)d_in[1];
    const float* Vy  = (const float*)d_in[2];
    const float* Vz  = (const float*)d_in[3];
    const float* Dxx = (const float*)d_in[4];
    const float* Dxy = (const float*)d_in[5];
    const float* Dxz = (const float*)d_in[6];
    const float* Dyy = (const float*)d_in[7];
    const float* Dyz = (const float*)d_in[8];
    const float* Dzz = (const float*)d_in[9];
    float* out = (float*)d_out;

    dim3 grid(NINT + NBND, 2);
    piano_all<<<grid, 160>>>(C, Vx, Vy, Vz, Dxx, Dxy, Dxz, Dyy, Dyz, Dzz, out);
}